// round 5
// baseline (speedup 1.0000x reference)
#include <cuda_runtime.h>
#include <cstdint>
#include <cstddef>

// LSTM autoencoder, fused persistent kernel, round 5.
// 128 CTAs x 512 threads; each CTA owns 2 batch elements.
// Every dot product is k-split across thread halves (hf = t>>8); each thread
// computes partials for BOTH batches over its k-half; partials combined at the
// activation phases through smem. Per-thread weight registers halve (96 regs),
// warps per SMSP double (4), total LDS traffic unchanged.

#define Tn 1024
#define NT 512

// smem float offsets
#define OFF_WA   0        // enc: Wih1 blocked [16c][256g][4]; dec: Whh1 blocked
#define OFF_WB   16384    // enc: Whh1 blocked; dec: FC blocked [16c][128o][4]
#define OFF_X    32768    // [2][2][128] x double-buffer
#define OFF_V    33280    // [2][2][128] parity, batch, (h0|h1)
#define OFF_G    33792    // [2(hf)][2(b)][256] gate partials
#define OFF_F    34816    // [2(hf)][256] fc partials
#define OFF_FCB  35328    // [128]
#define SMEM_FLOATS 35456 // 141824 bytes

__device__ __align__(16) float g_M[256 * 64];   // dec_Wih0 @ fcW

__device__ __forceinline__ void fma2(unsigned long long& acc,
                                     unsigned long long a, unsigned long long b) {
    asm("fma.rn.f32x2 %0, %1, %2, %3;" : "=l"(acc) : "l"(a), "l"(b), "l"(acc));
}
__device__ __forceinline__ float psum(unsigned long long v) {
    float lo, hi;
    asm("mov.b64 {%0, %1}, %2;" : "=f"(lo), "=f"(hi) : "l"(v));
    return lo + hi;
}
__device__ __forceinline__ float sigm_f(float v) {
    return __fdividef(1.f, 1.f + __expf(-v));
}
__device__ __forceinline__ float tanh_f(float v) {
    float a = fabsf(v);
    float e = __expf(-2.f * a);
    float r = __fdividef(1.f - e, 1.f + e);
    return v < 0.f ? -r : r;
}
__device__ __forceinline__ float cellact(float gi, float gf, float gg, float go, float& c) {
    c = sigm_f(gf) * c + sigm_f(gi) * tanh_f(gg);
    return sigm_f(go) * tanh_f(c);
}

__global__ void prep_kernel(const float* __restrict__ dW0i, const float* __restrict__ fcW) {
    int id = blockIdx.x * blockDim.x + threadIdx.x;  // 0..16383
    int g = id >> 6, j = id & 63;
    float acc = 0.f;
    #pragma unroll 4
    for (int d = 0; d < 128; d++)
        acc = fmaf(dW0i[g * 128 + d], fcW[d * 64 + j], acc);
    g_M[id] = acc;
}

// half-dot over blocked smem weights (stride 256 u2 per chunk), 8 chunks,
// both batch vectors. Returns partial sums.
__device__ __forceinline__ void halfdot256(const ulonglong2* __restrict__ wblk, int tt, int hf8,
                                           const ulonglong2* __restrict__ va,
                                           const ulonglong2* __restrict__ vb,
                                           float& r0, float& r1) {
    unsigned long long q0 = 0ull, q1 = 0ull;
    #pragma unroll
    for (int cc = 0; cc < 8; cc++) {
        int c = hf8 + cc;
        ulonglong2 w = wblk[c * 256 + tt];
        ulonglong2 xa = va[c], xb = vb[c];
        fma2(q0, w.x, xa.x); fma2(q0, w.y, xa.y);
        fma2(q1, w.x, xb.x); fma2(q1, w.y, xb.y);
    }
    r0 = psum(q0); r1 = psum(q1);
}

__global__ void __launch_bounds__(NT, 1)
lstm_ae_kernel(const float* __restrict__ x,
               const float* __restrict__ eW0i, const float* __restrict__ eW0h,
               const float* __restrict__ eb0i, const float* __restrict__ eb0h,
               const float* __restrict__ eW1i, const float* __restrict__ eW1h,
               const float* __restrict__ eb1i, const float* __restrict__ eb1h,
               const float* __restrict__ dW0i, const float* __restrict__ dW0h,
               const float* __restrict__ db0i, const float* __restrict__ db0h,
               const float* __restrict__ dW1i, const float* __restrict__ dW1h,
               const float* __restrict__ db1i, const float* __restrict__ db1h,
               const float* __restrict__ fcW,  const float* __restrict__ fcb,
               float* __restrict__ out)
{
    extern __shared__ float sm[];
    float* sWA  = sm + OFF_WA;
    float* sWB  = sm + OFF_WB;
    float* sX   = sm + OFF_X;
    float* sV   = sm + OFF_V;
    float* sG   = sm + OFF_G;
    float* sF   = sm + OFF_F;
    float* sFCb = sm + OFF_FCB;

    const int t  = threadIdx.x;
    const int b0 = blockIdx.x * 2;
    const int tt = t & 255;              // gate id / fc task id
    const int hf = t >> 8;               // k-half
    const int hf8 = hf * 8;
    const int aB = (t >> 6) & 1;         // act batch (t<128)
    const int aj = t & 63;               // act j

    float c0 = 0.f, c1 = 0.f;            // cell states (act threads t<128)

    // ================= ENCODER =================
    {
        unsigned long long w0h[48];      // this thread's 96-float half of [Wih0|Whh0] row tt
        if (hf == 0) {
            const ulonglong2* p = (const ulonglong2*)(eW0i + tt * 128);      // x[0:96]
            #pragma unroll
            for (int i = 0; i < 24; i++) { ulonglong2 v = p[i]; w0h[2*i] = v.x; w0h[2*i+1] = v.y; }
        } else {
            const ulonglong2* p = (const ulonglong2*)(eW0i + tt * 128 + 96); // x[96:128]
            #pragma unroll
            for (int i = 0; i < 8; i++) { ulonglong2 v = p[i]; w0h[2*i] = v.x; w0h[2*i+1] = v.y; }
            const ulonglong2* q = (const ulonglong2*)(eW0h + tt * 64);       // h0[0:64]
            #pragma unroll
            for (int i = 0; i < 16; i++) { ulonglong2 v = q[i]; w0h[16+2*i] = v.x; w0h[17+2*i] = v.y; }
        }
        const float bias0 = eb0i[tt] + eb0h[tt];
        const float bias1 = eb1i[tt] + eb1h[tt];

        // stage L1 weights blocked: chunk c of gate g at c*1024 + g*4
        for (int idx = t; idx < 256 * 64; idx += NT) {
            int g = idx >> 6, k = idx & 63;
            int c = k >> 2, m = k & 3;
            sWA[c * 1024 + g * 4 + m] = eW1i[idx];
            sWB[c * 1024 + g * 4 + m] = eW1h[idx];
        }
        sV[t] = 0.f;                      // zero both parity buffers (512 floats)

        // prefetch x steps 0,1
        #pragma unroll
        for (int s = 0; s < 2; s++) {
            if (t < 64) {
                int e = t >> 5, lane = t & 31;
                const float* src = x + ((size_t)(b0 + e) * Tn + s) * 128 + lane * 4;
                uint32_t dst = (uint32_t)__cvta_generic_to_shared(sX + (s * 2 + e) * 128 + lane * 4);
                asm volatile("cp.async.cg.shared.global [%0], [%1], 16;" :: "r"(dst), "l"(src) : "memory");
            }
            asm volatile("cp.async.commit_group;" ::: "memory");
        }
        asm volatile("cp.async.wait_group 1;" ::: "memory");
        __syncthreads();

        const ulonglong2* wip = (const ulonglong2*)sWA;
        const ulonglong2* whp = (const ulonglong2*)sWB;

        for (int s = 0; s < Tn; s++) {
            const int par = s & 1;
            const float* vR = sV + par * 256;
            float*       vW = sV + (par ^ 1) * 256;
            const float* xs = sX + par * 256;

            // ---- P1: L0 half-dots (both batches) + h1part half (Whh1) ----
            float p0, p1;   // h1part partials (carried to P3)
            {
                unsigned long long a0 = 0ull, a1 = 0ull;
                if (hf == 0) {
                    const ulonglong2* xa = (const ulonglong2*)(xs);
                    const ulonglong2* xb = (const ulonglong2*)(xs + 128);
                    #pragma unroll
                    for (int i = 0; i < 24; i++) {
                        ulonglong2 va = xa[i], vb = xb[i];
                        fma2(a0, w0h[2*i], va.x); fma2(a0, w0h[2*i+1], va.y);
                        fma2(a1, w0h[2*i], vb.x); fma2(a1, w0h[2*i+1], vb.y);
                    }
                } else {
                    const ulonglong2* xa = (const ulonglong2*)(xs + 96);
                    const ulonglong2* xb = (const ulonglong2*)(xs + 128 + 96);
                    #pragma unroll
                    for (int i = 0; i < 8; i++) {
                        ulonglong2 va = xa[i], vb = xb[i];
                        fma2(a0, w0h[2*i], va.x); fma2(a0, w0h[2*i+1], va.y);
                        fma2(a1, w0h[2*i], vb.x); fma2(a1, w0h[2*i+1], vb.y);
                    }
                    const ulonglong2* ha = (const ulonglong2*)(vR);
                    const ulonglong2* hb = (const ulonglong2*)(vR + 128);
                    #pragma unroll
                    for (int i = 0; i < 16; i++) {
                        ulonglong2 va = ha[i], vb = hb[i];
                        fma2(a0, w0h[16+2*i], va.x); fma2(a0, w0h[17+2*i], va.y);
                        fma2(a1, w0h[16+2*i], vb.x); fma2(a1, w0h[17+2*i], vb.y);
                    }
                }
                float ga = psum(a0), gb = psum(a1);
                if (hf == 0) { ga += bias0; gb += bias0; }
                sG[hf * 512 + tt]       = ga;
                sG[hf * 512 + 256 + tt] = gb;

                // h1part: h1[s-1] @ Whh1, k-half
                halfdot256(whp, tt, hf8,
                           (const ulonglong2*)(vR + 64), (const ulonglong2*)(vR + 192),
                           p0, p1);
                if (hf == 0) { p0 += bias1; p1 += bias1; }
            }
            __syncthreads();

            // ---- P2: act0 (t<128) + x prefetch (t in [256,320)) ----
            if (t < 128) {
                const float* gl = sG + aB * 256;
                const float* gh = sG + 512 + aB * 256;
                float gi = gl[aj]       + gh[aj];
                float gf = gl[64 + aj]  + gh[64 + aj];
                float gg = gl[128 + aj] + gh[128 + aj];
                float go = gl[192 + aj] + gh[192 + aj];
                vW[aB * 128 + aj] = cellact(gi, gf, gg, go, c0);
            } else if (t < 320 && t >= 256 && s + 2 < Tn) {
                int tt2 = t - 256, e = tt2 >> 5, lane = tt2 & 31;
                const float* src = x + ((size_t)(b0 + e) * Tn + (s + 2)) * 128 + lane * 4;
                uint32_t dst = (uint32_t)__cvta_generic_to_shared(sX + (par * 2 + e) * 128 + lane * 4);
                asm volatile("cp.async.cg.shared.global [%0], [%1], 16;" :: "r"(dst), "l"(src) : "memory");
            }
            asm volatile("cp.async.commit_group;" ::: "memory");
            __syncthreads();

            // ---- P3: L1 half-dots = h0[s] @ Wih1 (k-half) + h1part ----
            {
                float q0, q1;
                halfdot256(wip, tt, hf8,
                           (const ulonglong2*)(vW), (const ulonglong2*)(vW + 128),
                           q0, q1);
                sG[hf * 512 + tt]       = q0 + p0;
                sG[hf * 512 + 256 + tt] = q1 + p1;
            }
            __syncthreads();

            // ---- P4: act1 (t<128) ----
            if (t < 128) {
                const float* gl = sG + aB * 256;
                const float* gh = sG + 512 + aB * 256;
                float gi = gl[aj]       + gh[aj];
                float gf = gl[64 + aj]  + gh[64 + aj];
                float gg = gl[128 + aj] + gh[128 + aj];
                float go = gl[192 + aj] + gh[192 + aj];
                vW[aB * 128 + 64 + aj] = cellact(gi, gf, gg, go, c1);
            }
            asm volatile("cp.async.wait_group 1;" ::: "memory");
            __syncthreads();
        }
        asm volatile("cp.async.wait_group 0;" ::: "memory");
    }

    // ================= TRANSITION =================
    // encoder final state (s=1023, par=1) was written to buffer 0.
    if (t < 128) {
        c0 = tanh_f(c0);
        c1 = tanh_f(c1);
        sV[aB * 128 + aj]      = tanh_f(sV[aB * 128 + aj]);
        sV[aB * 128 + 64 + aj] = tanh_f(sV[aB * 128 + 64 + aj]);
    }
    unsigned long long wHh[16];   // Whh0 half (32 fl over h0)
    unsigned long long wMh[16];   // M half    (32 fl over h1)
    unsigned long long wIh[16];   // Wih1 half (32 fl over h0)
    {
        const ulonglong2* p = (const ulonglong2*)(dW0h + tt * 64 + hf * 32);
        #pragma unroll
        for (int i = 0; i < 8; i++) { ulonglong2 v = p[i]; wHh[2*i] = v.x; wHh[2*i+1] = v.y; }
        const ulonglong2* q = (const ulonglong2*)(g_M + tt * 64 + hf * 32);
        #pragma unroll
        for (int i = 0; i < 8; i++) { ulonglong2 v = q[i]; wMh[2*i] = v.x; wMh[2*i+1] = v.y; }
        const ulonglong2* r = (const ulonglong2*)(dW1i + tt * 64 + hf * 32);
        #pragma unroll
        for (int i = 0; i < 8; i++) { ulonglong2 v = r[i]; wIh[2*i] = v.x; wIh[2*i+1] = v.y; }
    }
    const float bias0d = db0i[tt] + db0h[tt];
    float b0fold;
    {
        float a = 0.f;
        #pragma unroll 4
        for (int d = 0; d < 128; d++) a = fmaf(dW0i[tt * 128 + d], fcb[d], a);
        b0fold = bias0d + a;
    }
    const float bias1d = db1i[tt] + db1h[tt];
    __syncthreads();   // encoder reads of sWA/sWB done before overwrite
    for (int idx = t; idx < 256 * 64; idx += NT) {
        int g = idx >> 6, k = idx & 63;
        sWA[(k >> 2) * 1024 + g * 4 + (k & 3)] = dW1h[idx];
    }
    for (int idx = t; idx < 128 * 64; idx += NT) {
        int o = idx >> 6, k = idx & 63;
        sWB[(k >> 2) * 512 + o * 4 + (k & 3)] = fcW[idx];
    }
    if (t < 128) sFCb[t] = fcb[t];
    __syncthreads();

    // ================= DECODER =================
    const int oF = tt & 127, bFc = tt >> 7;     // FC task for this thread
    const ulonglong2* whp = (const ulonglong2*)sWA;   // Whh1 blocked
    const ulonglong2* wfc = (const ulonglong2*)sWB;   // FC blocked [c*128 + o]
    const float fcbO = sFCb[oF];

    for (int s = 0; s < Tn; s++) {
        const int par = s & 1;
        const float* vR = sV + par * 256;
        float*       vW = sV + (par ^ 1) * 256;

        // ---- P1: gates0 half-dots + h1part half + deferred-FC half ----
        float p0, p1;
        {
            const ulonglong2* h0a = (const ulonglong2*)(vR + hf * 32);
            const ulonglong2* h0b = (const ulonglong2*)(vR + 128 + hf * 32);
            const ulonglong2* h1a = (const ulonglong2*)(vR + 64 + hf * 32);
            const ulonglong2* h1b = (const ulonglong2*)(vR + 192 + hf * 32);
            unsigned long long a0 = 0ull, a1 = 0ull;
            #pragma unroll
            for (int i = 0; i < 8; i++) {
                ulonglong2 va = h0a[i], vb = h0b[i];
                fma2(a0, wHh[2*i], va.x); fma2(a0, wHh[2*i+1], va.y);
                fma2(a1, wHh[2*i], vb.x); fma2(a1, wHh[2*i+1], vb.y);
            }
            if (s > 0) {
                #pragma unroll
                for (int i = 0; i < 8; i++) {
                    ulonglong2 va = h1a[i], vb = h1b[i];
                    fma2(a0, wMh[2*i], va.x); fma2(a0, wMh[2*i+1], va.y);
                    fma2(a1, wMh[2*i], vb.x); fma2(a1, wMh[2*i+1], vb.y);
                }
            }
            float ga = psum(a0), gb = psum(a1);
            if (hf == 0) {
                float bb = (s > 0) ? b0fold : bias0d;
                ga += bb; gb += bb;
            }
            sG[hf * 512 + tt]       = ga;
            sG[hf * 512 + 256 + tt] = gb;

            // h1part (Whh1 smem, k-half)
            halfdot256(whp, tt, hf8,
                       (const ulonglong2*)(vR + 64), (const ulonglong2*)(vR + 192),
                       p0, p1);
            if (hf == 0) { p0 += bias1d; p1 += bias1d; }

            // deferred FC of h1[s-1], k-half
            if (s > 0) {
                const ulonglong2* hp = (const ulonglong2*)(vR + bFc * 128 + 64);
                unsigned long long f0 = 0ull;
                #pragma unroll
                for (int cc = 0; cc < 8; cc++) {
                    int c = hf8 + cc;
                    ulonglong2 w = wfc[c * 128 + oF];
                    ulonglong2 h = hp[c];
                    fma2(f0, w.x, h.x); fma2(f0, w.y, h.y);
                }
                float pf = psum(f0);
                if (hf == 0) pf += fcbO;
                sF[hf * 256 + tt] = pf;
            }
        }
        __syncthreads();

        // ---- P2: act0 (t<128) + FC combine/store (t in [128,384)) ----
        if (t < 128) {
            const float* gl = sG + aB * 256;
            const float* gh = sG + 512 + aB * 256;
            float gi = gl[aj]       + gh[aj];
            float gf = gl[64 + aj]  + gh[64 + aj];
            float gg = gl[128 + aj] + gh[128 + aj];
            float go = gl[192 + aj] + gh[192 + aj];
            vW[aB * 128 + aj] = cellact(gi, gf, gg, go, c0);
        } else if (t < 384 && s > 0) {
            int idx = t - 128;
            int o = idx & 127, bb = idx >> 7;
            float pr = sF[idx] + sF[256 + idx];
            out[((size_t)(b0 + bb) * Tn + (s - 1)) * 128 + o] = pr;
        }
        __syncthreads();

        // ---- P3: gates1 half-dots = h0[s] @ Wih1-half (regs) + p ----
        {
            const ulonglong2* h0a = (const ulonglong2*)(vW + hf * 32);
            const ulonglong2* h0b = (const ulonglong2*)(vW + 128 + hf * 32);
            unsigned long long a0 = 0ull, a1 = 0ull;
            #pragma unroll
            for (int i = 0; i < 8; i++) {
                ulonglong2 va = h0a[i], vb = h0b[i];
                fma2(a0, wIh[2*i], va.x); fma2(a0, wIh[2*i+1], va.y);
                fma2(a1, wIh[2*i], vb.x); fma2(a1, wIh[2*i+1], vb.y);
            }
            sG[hf * 512 + tt]       = psum(a0) + p0;
            sG[hf * 512 + 256 + tt] = psum(a1) + p1;
        }
        __syncthreads();

        // ---- P4: act1 (t<128) ----
        if (t < 128) {
            const float* gl = sG + aB * 256;
            const float* gh = sG + 512 + aB * 256;
            float gi = gl[aj]       + gh[aj];
            float gf = gl[64 + aj]  + gh[64 + aj];
            float gg = gl[128 + aj] + gh[128 + aj];
            float go = gl[192 + aj] + gh[192 + aj];
            vW[aB * 128 + 64 + aj] = cellact(gi, gf, gg, go, c1);
        }
        __syncthreads();
    }

    // final FC for h1[T-1] (in buffer 0 after s=1023)
    {
        const ulonglong2* hp = (const ulonglong2*)(sV + bFc * 128 + 64);
        unsigned long long f0 = 0ull;
        #pragma unroll
        for (int cc = 0; cc < 8; cc++) {
            int c = hf8 + cc;
            ulonglong2 w = wfc[c * 128 + oF];
            ulonglong2 h = hp[c];
            fma2(f0, w.x, h.x); fma2(f0, w.y, h.y);
        }
        float pf = psum(f0);
        if (hf == 0) pf += fcbO;
        sF[hf * 256 + tt] = pf;
    }
    __syncthreads();
    if (t >= 128 && t < 384) {
        int idx = t - 128;
        int o = idx & 127, bb = idx >> 7;
        float pr = sF[idx] + sF[256 + idx];
        out[((size_t)(b0 + bb) * Tn + (Tn - 1)) * 128 + o] = pr;
    }
}

extern "C" void kernel_launch(void* const* d_in, const int* in_sizes, int n_in,
                              void* d_out, int out_size) {
    (void)in_sizes; (void)n_in; (void)out_size;
    const float* x    = (const float*)d_in[0];
    const float* eW0i = (const float*)d_in[1];
    const float* eW0h = (const float*)d_in[2];
    const float* eb0i = (const float*)d_in[3];
    const float* eb0h = (const float*)d_in[4];
    const float* eW1i = (const float*)d_in[5];
    const float* eW1h = (const float*)d_in[6];
    const float* eb1i = (const float*)d_in[7];
    const float* eb1h = (const float*)d_in[8];
    const float* dW0i = (const float*)d_in[9];
    const float* dW0h = (const float*)d_in[10];
    const float* db0i = (const float*)d_in[11];
    const float* db0h = (const float*)d_in[12];
    const float* dW1i = (const float*)d_in[13];
    const float* dW1h = (const float*)d_in[14];
    const float* db1i = (const float*)d_in[15];
    const float* db1h = (const float*)d_in[16];
    const float* fcW  = (const float*)d_in[17];
    const float* fcb  = (const float*)d_in[18];

    prep_kernel<<<64, 256>>>(dW0i, fcW);

    cudaFuncSetAttribute(lstm_ae_kernel, cudaFuncAttributeMaxDynamicSharedMemorySize,
                         SMEM_FLOATS * (int)sizeof(float));
    lstm_ae_kernel<<<128, NT, SMEM_FLOATS * sizeof(float)>>>(
        x, eW0i, eW0h, eb0i, eb0h, eW1i, eW1h, eb1i, eb1h,
        dW0i, dW0h, db0i, db0h, dW1i, dW1h, db1i, db1h,
        fcW, fcb, (float*)d_out);
}

// round 6
// speedup vs baseline: 1.1655x; 1.1655x over previous
#include <cuda_runtime.h>
#include <cstdint>
#include <cstddef>

// LSTM autoencoder, fused persistent kernel, round 6.
// R6 = R4 decoder + new encoder: the non-recurrent x@Wih0^T GEMM is hoisted
// into a precompute kernel (g_XW, bias folded). Encoder recurrent loop keeps
// ALL weights (Whh0, Wih1, Whh1 rows) in registers; per-step smem traffic is
// h-vector broadcasts + 2 XW floats streamed via cp.async.
// 128 CTAs x 256 threads; each CTA owns 2 batch elements.

#define Tn 1024

// smem float offsets
#define OFF_WA   0        // dec Whh1 blocked [16c][256g][4]
#define OFF_WB   16384    // dec FC blocked [16c][128o][4] (8192) + fcb @ +8192
#define OFF_XW   24704    // [2][512] XW double buffer
#define OFF_V    25728    // [2][128] per-batch [h0(64)|h1(64)]
#define OFF_G    25984    // [2][256] gate scratch
#define SMEM_FLOATS 26496 // 105984 bytes

__device__ __align__(16) float g_M[256 * 64];            // dec_Wih0 @ fcW
__device__ __align__(16) float g_XW[128u * 1024u * 512u]; // enc L0 x-part, bias folded

__device__ __forceinline__ void fma2(unsigned long long& acc,
                                     unsigned long long a, unsigned long long b) {
    asm("fma.rn.f32x2 %0, %1, %2, %3;" : "=l"(acc) : "l"(a), "l"(b), "l"(acc));
}
__device__ __forceinline__ float psum(unsigned long long v) {
    float lo, hi;
    asm("mov.b64 {%0, %1}, %2;" : "=f"(lo), "=f"(hi) : "l"(v));
    return lo + hi;
}
__device__ __forceinline__ float sigm_f(float v) {
    return __fdividef(1.f, 1.f + __expf(-v));
}
__device__ __forceinline__ float tanh_f(float v) {
    float a = fabsf(v);
    float e = __expf(-2.f * a);
    float r = __fdividef(1.f - e, 1.f + e);
    return v < 0.f ? -r : r;
}
__device__ __forceinline__ float cellact(float gi, float gf, float gg, float go, float& c) {
    c = sigm_f(gf) * c + sigm_f(gi) * tanh_f(gg);
    return sigm_f(go) * tanh_f(c);
}

__global__ void prep_kernel(const float* __restrict__ dW0i, const float* __restrict__ fcW) {
    int id = blockIdx.x * blockDim.x + threadIdx.x;  // 0..16383
    int g = id >> 6, j = id & 63;
    float acc = 0.f;
    #pragma unroll 4
    for (int d = 0; d < 128; d++)
        acc = fmaf(dW0i[g * 128 + d], fcW[d * 64 + j], acc);
    g_M[id] = acc;
}

// XW[pair][s][e][g] = x[b,s,:] . Wih0[g,:] + eb0i[g] + eb0h[g]
__global__ void __launch_bounds__(256, 1)
prep_x_kernel(const float* __restrict__ x, const float* __restrict__ eW0i,
              const float* __restrict__ eb0i, const float* __restrict__ eb0h) {
    __shared__ float sx[32 * 128];
    const int b  = blockIdx.x;     // 0..255
    const int ch = blockIdx.y;     // 0..31 (32-step chunk)
    const int t  = threadIdx.x;    // gate 0..255

    for (int i = t; i < 32 * 128; i += 256)
        sx[i] = x[((size_t)b * Tn + ch * 32) * 128 + i];

    unsigned long long w[64];
    const ulonglong2* p = (const ulonglong2*)(eW0i + t * 128);
    #pragma unroll
    for (int i = 0; i < 32; i++) { ulonglong2 v = p[i]; w[2*i] = v.x; w[2*i+1] = v.y; }
    const float bias = eb0i[t] + eb0h[t];
    __syncthreads();

    for (int s = 0; s < 32; s++) {
        const ulonglong2* xp = (const ulonglong2*)(sx + s * 128);
        unsigned long long q0 = 0ull, q1 = 0ull;
        #pragma unroll
        for (int i = 0; i < 32; i++) {
            ulonglong2 v = xp[i];
            fma2(q0, w[2*i], v.x);
            fma2(q1, w[2*i+1], v.y);
        }
        g_XW[(((size_t)(b >> 1) * Tn + ch * 32 + s) * 2 + (b & 1)) * 256 + t] =
            psum(q0) + psum(q1) + bias;
    }
}

__global__ void __launch_bounds__(256, 1)
lstm_ae_kernel(const float* __restrict__ x,
               const float* __restrict__ eW0i, const float* __restrict__ eW0h,
               const float* __restrict__ eb0i, const float* __restrict__ eb0h,
               const float* __restrict__ eW1i, const float* __restrict__ eW1h,
               const float* __restrict__ eb1i, const float* __restrict__ eb1h,
               const float* __restrict__ dW0i, const float* __restrict__ dW0h,
               const float* __restrict__ db0i, const float* __restrict__ db0h,
               const float* __restrict__ dW1i, const float* __restrict__ dW1h,
               const float* __restrict__ db1i, const float* __restrict__ db1h,
               const float* __restrict__ fcW,  const float* __restrict__ fcb,
               float* __restrict__ out)
{
    extern __shared__ float sm[];
    float* sWA  = sm + OFF_WA;
    float* sWB  = sm + OFF_WB;
    float* sFCb = sm + OFF_WB + 8192;
    float* sXW  = sm + OFF_XW;
    float* sV   = sm + OFF_V;
    float* sG   = sm + OFF_G;

    const int t  = threadIdx.x;
    const int b0 = blockIdx.x * 2;
    const int aj = t & 63;
    const int ab = (t >> 6) & 1;

    float c0 = 0.f, c1 = 0.f;

    // ---- stage decoder smem weights up front (encoder doesn't use sWA/sWB) ----
    for (int idx = t; idx < 256 * 64; idx += 256) {
        int g = idx >> 6, k = idx & 63;
        sWA[(k >> 2) * 1024 + g * 4 + (k & 3)] = dW1h[idx];
    }
    for (int idx = t; idx < 128 * 64; idx += 256) {
        int o = idx >> 6, k = idx & 63;
        sWB[(k >> 2) * 512 + o * 4 + (k & 3)] = fcW[idx];
    }
    if (t < 128) sFCb[t] = fcb[t];

    // ================= ENCODER =================
    {
        unsigned long long wH0[32], wI1[32], wH1[32];   // rows t of Whh0, Wih1, Whh1
        {
            const ulonglong2* p = (const ulonglong2*)(eW0h + t * 64);
            #pragma unroll
            for (int i = 0; i < 16; i++) { ulonglong2 v = p[i]; wH0[2*i] = v.x; wH0[2*i+1] = v.y; }
            const ulonglong2* q = (const ulonglong2*)(eW1i + t * 64);
            #pragma unroll
            for (int i = 0; i < 16; i++) { ulonglong2 v = q[i]; wI1[2*i] = v.x; wI1[2*i+1] = v.y; }
            const ulonglong2* r = (const ulonglong2*)(eW1h + t * 64);
            #pragma unroll
            for (int i = 0; i < 16; i++) { ulonglong2 v = r[i]; wH1[2*i] = v.x; wH1[2*i+1] = v.y; }
        }
        const float bias1 = eb1i[t] + eb1h[t];
        sV[t] = 0.f;   // zero h state (256 floats)

        const size_t xwbase = (size_t)blockIdx.x * Tn * 512;

        // prologue: prefetch XW for steps 0,1
        #pragma unroll
        for (int s = 0; s < 2; s++) {
            if (t < 128) {
                const float* src = g_XW + xwbase + (size_t)s * 512 + t * 4;
                uint32_t dst = (uint32_t)__cvta_generic_to_shared(sXW + s * 512 + t * 4);
                asm volatile("cp.async.cg.shared.global [%0], [%1], 16;" :: "r"(dst), "l"(src) : "memory");
            }
            asm volatile("cp.async.commit_group;" ::: "memory");
        }
        asm volatile("cp.async.wait_group 1;" ::: "memory");
        __syncthreads();

        for (int s = 0; s < Tn; s++) {
            const int par = s & 1;
            const float* xw = sXW + par * 512;

            // ---- P1: gates0 = XW + h0_prev@Whh0 ; h1part = h1_prev@Whh1 + bias1 ----
            float p0, p1;
            {
                const ulonglong2* h0a = (const ulonglong2*)(sV);
                const ulonglong2* h0b = (const ulonglong2*)(sV + 128);
                unsigned long long qa0 = 0, qa1 = 0, qb0 = 0, qb1 = 0;
                #pragma unroll
                for (int i = 0; i < 16; i++) {
                    ulonglong2 va = h0a[i], vb = h0b[i];
                    fma2(qa0, wH0[2*i], va.x); fma2(qa1, wH0[2*i+1], va.y);
                    fma2(qb0, wH0[2*i], vb.x); fma2(qb1, wH0[2*i+1], vb.y);
                }
                float ga = xw[t]       + psum(qa0) + psum(qa1);
                float gb = xw[256 + t] + psum(qb0) + psum(qb1);

                const ulonglong2* h1a = (const ulonglong2*)(sV + 64);
                const ulonglong2* h1b = (const ulonglong2*)(sV + 192);
                unsigned long long r0 = 0, r1 = 0, r2 = 0, r3 = 0;
                #pragma unroll
                for (int i = 0; i < 16; i++) {
                    ulonglong2 va = h1a[i], vb = h1b[i];
                    fma2(r0, wH1[2*i], va.x); fma2(r1, wH1[2*i+1], va.y);
                    fma2(r2, wH1[2*i], vb.x); fma2(r3, wH1[2*i+1], vb.y);
                }
                p0 = psum(r0) + psum(r1) + bias1;
                p1 = psum(r2) + psum(r3) + bias1;
                sG[t] = ga; sG[256 + t] = gb;
            }
            __syncthreads();

            // ---- P2: act0 (t<128) | prefetch XW[s+2] (t>=128) ----
            if (t < 128) {
                const float* g = sG + ab * 256;
                sV[ab * 128 + aj] = cellact(g[aj], g[64 + aj], g[128 + aj], g[192 + aj], c0);
            } else if (s + 2 < Tn) {
                int l = t - 128;
                const float* src = g_XW + xwbase + (size_t)(s + 2) * 512 + l * 4;
                uint32_t dst = (uint32_t)__cvta_generic_to_shared(sXW + par * 512 + l * 4);
                asm volatile("cp.async.cg.shared.global [%0], [%1], 16;" :: "r"(dst), "l"(src) : "memory");
            }
            asm volatile("cp.async.commit_group;" ::: "memory");
            __syncthreads();

            // ---- P3: gates1 = h0[s]@Wih1 + h1part ----
            {
                const ulonglong2* h0a = (const ulonglong2*)(sV);
                const ulonglong2* h0b = (const ulonglong2*)(sV + 128);
                unsigned long long qa0 = 0, qa1 = 0, qb0 = 0, qb1 = 0;
                #pragma unroll
                for (int i = 0; i < 16; i++) {
                    ulonglong2 va = h0a[i], vb = h0b[i];
                    fma2(qa0, wI1[2*i], va.x); fma2(qa1, wI1[2*i+1], va.y);
                    fma2(qb0, wI1[2*i], vb.x); fma2(qb1, wI1[2*i+1], vb.y);
                }
                sG[t]       = psum(qa0) + psum(qa1) + p0;
                sG[256 + t] = psum(qb0) + psum(qb1) + p1;
            }
            __syncthreads();

            // ---- P4: act1 ----
            if (t < 128) {
                const float* g = sG + ab * 256;
                sV[ab * 128 + 64 + aj] = cellact(g[aj], g[64 + aj], g[128 + aj], g[192 + aj], c1);
            }
            asm volatile("cp.async.wait_group 1;" ::: "memory");
            __syncthreads();
        }
        asm volatile("cp.async.wait_group 0;" ::: "memory");
    }

    // ================= TRANSITION =================
    if (t < 128) {
        c0 = tanh_f(c0);
        c1 = tanh_f(c1);
        sV[ab * 128 + aj]      = tanh_f(sV[ab * 128 + aj]);
        sV[ab * 128 + 64 + aj] = tanh_f(sV[ab * 128 + 64 + aj]);
    }
    unsigned long long wA[64];  // [0..31] M row (over h1), [32..63] Whh0 row (over h0)
    unsigned long long wC[32];  // Wih1 row (over h0)
    {
        const ulonglong2* p = (const ulonglong2*)(g_M + t * 64);
        #pragma unroll
        for (int i = 0; i < 16; i++) { ulonglong2 v = p[i]; wA[2*i] = v.x; wA[2*i+1] = v.y; }
        const ulonglong2* q = (const ulonglong2*)(dW0h + t * 64);
        #pragma unroll
        for (int i = 0; i < 16; i++) { ulonglong2 v = q[i]; wA[32+2*i] = v.x; wA[33+2*i] = v.y; }
        const ulonglong2* r = (const ulonglong2*)(dW1i + t * 64);
        #pragma unroll
        for (int i = 0; i < 16; i++) { ulonglong2 v = r[i]; wC[2*i] = v.x; wC[2*i+1] = v.y; }
    }
    const float bias0 = db0i[t] + db0h[t];
    float b0fold;
    {
        float a = 0.f;
        #pragma unroll 4
        for (int d = 0; d < 128; d++) a = fmaf(dW0i[t * 128 + d], fcb[d], a);
        b0fold = bias0 + a;   // bias0 + Wih0 @ fcb
    }
    const float bias1 = db1i[t] + db1h[t];
    __syncthreads();

    // ================= DECODER (R4-verbatim) =================
    const int oF = t & 127, bF = t >> 7;
    const ulonglong2* whp = (const ulonglong2*)sWA;   // Whh1 blocked [c*256 + t]
    const ulonglong2* wfc = (const ulonglong2*)sWB;   // FC blocked  [c*128 + oF]
    const float fcbO = sFCb[oF];

    for (int step = 0; step < Tn; step++) {
        // P1: gates0 = Whh0*h0_prev (+ M*h1_prev if step>0) + deferred FC -> out[step-1]
        {
            const ulonglong2* h0a = (const ulonglong2*)(sV);
            const ulonglong2* h0b = (const ulonglong2*)(sV + 128);
            const ulonglong2* h1a = (const ulonglong2*)(sV + 64);
            const ulonglong2* h1b = (const ulonglong2*)(sV + 192);
            unsigned long long a0 = 0, a1 = 0, c0q = 0, c1q = 0;
            #pragma unroll
            for (int i = 0; i < 16; i++) {
                ulonglong2 va = h0a[i]; ulonglong2 vb = h0b[i];
                fma2(a0, wA[32 + 2*i], va.x); fma2(a1, wA[33 + 2*i], va.y);
                fma2(c0q, wA[32 + 2*i], vb.x); fma2(c1q, wA[33 + 2*i], vb.y);
            }
            float ga, gb;
            if (step > 0) {
                #pragma unroll
                for (int i = 0; i < 16; i++) {
                    ulonglong2 va = h1a[i]; ulonglong2 vb = h1b[i];
                    fma2(a0, wA[2*i], va.x); fma2(a1, wA[2*i+1], va.y);
                    fma2(c0q, wA[2*i], vb.x); fma2(c1q, wA[2*i+1], vb.y);
                }
                ga = psum(a0) + psum(a1) + b0fold;
                gb = psum(c0q) + psum(c1q) + b0fold;
                // deferred FC of previous h1
                const ulonglong2* hp = (const ulonglong2*)(sV + bF * 128 + 64);
                unsigned long long f0 = 0, f1 = 0;
                #pragma unroll
                for (int i = 0; i < 8; i++) {
                    ulonglong2 wc0 = wfc[(2*i) * 128 + oF];
                    ulonglong2 wc1 = wfc[(2*i+1) * 128 + oF];
                    ulonglong2 h0v = hp[2*i], h1v = hp[2*i+1];
                    fma2(f0, wc0.x, h0v.x); fma2(f1, wc0.y, h0v.y);
                    fma2(f0, wc1.x, h1v.x); fma2(f1, wc1.y, h1v.y);
                }
                float pr = psum(f0) + psum(f1) + fcbO;
                out[((size_t)(b0 + bF) * Tn + (step - 1)) * 128 + oF] = pr;
            } else {
                ga = psum(a0) + psum(a1) + bias0;
                gb = psum(c0q) + psum(c1q) + bias0;
            }
            sG[t] = ga; sG[256 + t] = gb;
        }
        __syncthreads();

        // P2: act0 + h1part (h1_prev @ Whh1, blocked smem)
        float p0, p1;
        {
            const ulonglong2* h1a = (const ulonglong2*)(sV + 64);
            const ulonglong2* h1b = (const ulonglong2*)(sV + 192);
            unsigned long long q00 = 0, q01 = 0, q10 = 0, q11 = 0;
            #pragma unroll
            for (int i = 0; i < 8; i++) {
                ulonglong2 w0c = whp[(2*i) * 256 + t];
                ulonglong2 w1c = whp[(2*i+1) * 256 + t];
                ulonglong2 va0 = h1a[2*i], va1 = h1a[2*i+1];
                ulonglong2 vb0 = h1b[2*i], vb1 = h1b[2*i+1];
                fma2(q00, w0c.x, va0.x); fma2(q01, w0c.y, va0.y);
                fma2(q10, w0c.x, vb0.x); fma2(q11, w0c.y, vb0.y);
                fma2(q00, w1c.x, va1.x); fma2(q01, w1c.y, va1.y);
                fma2(q10, w1c.x, vb1.x); fma2(q11, w1c.y, vb1.y);
            }
            p0 = psum(q00) + psum(q01);
            p1 = psum(q10) + psum(q11);
        }
        if (t < 128) {
            const float* g = sG + ab * 256;
            sV[ab * 128 + aj] = cellact(g[aj], g[64 + aj], g[128 + aj], g[192 + aj], c0);
        }
        __syncthreads();

        // P3: gates1 = h0 @ Wih1 (regs) + h1part
        {
            const ulonglong2* h0a = (const ulonglong2*)(sV);
            const ulonglong2* h0b = (const ulonglong2*)(sV + 128);
            unsigned long long q00 = 0, q01 = 0, q10 = 0, q11 = 0;
            #pragma unroll
            for (int i = 0; i < 16; i++) {
                ulonglong2 va = h0a[i]; ulonglong2 vb = h0b[i];
                fma2(q00, wC[2*i], va.x); fma2(q01, wC[2*i+1], va.y);
                fma2(q10, wC[2*i], vb.x); fma2(q11, wC[2*i+1], vb.y);
            }
            sG[t]       = psum(q00) + psum(q01) + p0 + bias1;
            sG[256 + t] = psum(q10) + psum(q11) + p1 + bias1;
        }
        __syncthreads();

        // P4: act1
        if (t < 128) {
            const float* g = sG + ab * 256;
            sV[ab * 128 + 64 + aj] = cellact(g[aj], g[64 + aj], g[128 + aj], g[192 + aj], c1);
        }
        __syncthreads();
    }

    // final FC for last step's h1
    {
        const ulonglong2* hp = (const ulonglong2*)(sV + bF * 128 + 64);
        unsigned long long f0 = 0, f1 = 0;
        #pragma unroll
        for (int i = 0; i < 8; i++) {
            ulonglong2 wc0 = wfc[(2*i) * 128 + oF];
            ulonglong2 wc1 = wfc[(2*i+1) * 128 + oF];
            ulonglong2 h0v = hp[2*i], h1v = hp[2*i+1];
            fma2(f0, wc0.x, h0v.x); fma2(f1, wc0.y, h0v.y);
            fma2(f0, wc1.x, h1v.x); fma2(f1, wc1.y, h1v.y);
        }
        float pr = psum(f0) + psum(f1) + fcbO;
        out[((size_t)(b0 + bF) * Tn + (Tn - 1)) * 128 + oF] = pr;
    }
}

extern "C" void kernel_launch(void* const* d_in, const int* in_sizes, int n_in,
                              void* d_out, int out_size) {
    (void)in_sizes; (void)n_in; (void)out_size;
    const float* x    = (const float*)d_in[0];
    const float* eW0i = (const float*)d_in[1];
    const float* eW0h = (const float*)d_in[2];
    const float* eb0i = (const float*)d_in[3];
    const float* eb0h = (const float*)d_in[4];
    const float* eW1i = (const float*)d_in[5];
    const float* eW1h = (const float*)d_in[6];
    const float* eb1i = (const float*)d_in[7];
    const float* eb1h = (const float*)d_in[8];
    const float* dW0i = (const float*)d_in[9];
    const float* dW0h = (const float*)d_in[10];
    const float* db0i = (const float*)d_in[11];
    const float* db0h = (const float*)d_in[12];
    const float* dW1i = (const float*)d_in[13];
    const float* dW1h = (const float*)d_in[14];
    const float* db1i = (const float*)d_in[15];
    const float* db1h = (const float*)d_in[16];
    const float* fcW  = (const float*)d_in[17];
    const float* fcb  = (const float*)d_in[18];

    prep_kernel<<<64, 256>>>(dW0i, fcW);
    dim3 pgrid(256, 32);
    prep_x_kernel<<<pgrid, 256>>>(x, eW0i, eb0i, eb0h);

    cudaFuncSetAttribute(lstm_ae_kernel, cudaFuncAttributeMaxDynamicSharedMemorySize,
                         SMEM_FLOATS * (int)sizeof(float));
    lstm_ae_kernel<<<128, 256, SMEM_FLOATS * sizeof(float)>>>(
        x, eW0i, eW0h, eb0i, eb0h, eW1i, eW1h, eb1i, eb1h,
        dW0i, dW0h, db0i, db0h, dW1i, dW1h, db1i, db1h,
        fcW, fcb, (float*)d_out);
}